// round 7
// baseline (speedup 1.0000x reference)
#include <cuda_runtime.h>
#include <math.h>

#define NB 128
#define NP 625
#define NENC 512
#define NA 256
#define NE 256
#define NH 512
#define NV 70
#define NT 70
#define NG 2048
#define KC 64
#define START_TOK 68
#define END_TOK 69

// ---------------- scratch ----------------
__device__ float g_att1[NB * NP * NA];   // 81.92MB
__device__ float g_h[NB * NH];
__device__ float g_c[NB * NH];
__device__ float g_mean[NB * NENC];
__device__ float g_x[NB * NH];           // gated awe
__device__ float g_a2p[4][NB * NA];      // att2 K-partials
__device__ float g_gtp[4][NB * NENC];    // gate  K-partials
__device__ float g_gw[2][NB * NG];       // h@Whh K-partials
__device__ float g_wp[2][NB * NG];       // awe@Wih2 K-partials
__device__ float g_embW[NV * NG];        // emb @ Wih[0:256] per vocab token
__device__ float g_lstmb[NG];            // bih + bhh
__device__ float g_WfcT[NV * NH];
__device__ float g_rowval[NB];
__device__ int   g_rowflat[NB];
__device__ int   g_tok[NB];
__device__ int   g_done[1];

// ---------------- f32x2 helpers ----------------
__device__ __forceinline__ unsigned long long fma2(unsigned long long a, unsigned long long b,
                                                   unsigned long long c) {
    unsigned long long d;
    asm("fma.rn.f32x2 %0, %1, %2, %3;" : "=l"(d) : "l"(a), "l"(b), "l"(c));
    return d;
}
__device__ __forceinline__ float2 unpack2(unsigned long long v) {
    float2 r;
    asm("mov.b64 {%0, %1}, %2;" : "=f"(r.x), "=f"(r.y) : "l"(v));
    return r;
}
__device__ __forceinline__ float sigmoidf_(float x) { return 1.f / (1.f + expf(-x)); }

// ---------------- core GEMM tile: C[128, c0:c0+32] = A[128,K] @ W[K, ldw] ----------------
// 256 threads, K % 64 == 0, double-buffered via registers, vector LDS.128 inner loop.
__device__ __forceinline__ void gemm128x32(const float* __restrict__ A, int lda,
                                           const float* __restrict__ W, int ldw, int c0, int K,
                                           unsigned long long acc[8], float* As, float2* Bs) {
    const int tid = threadIdx.x;
    const int ai = (tid >> 4) * 2;   // ull2 index into A k-row (m-pairs)
    const int bi = tid & 15;         // ull2 index into B k-row (n-pairs)
    const int la_m = tid & 127, la_k = (tid >> 7) * 32;
    const int lb_n = tid & 31, lb_k = tid >> 5;
#pragma unroll
    for (int j = 0; j < 8; j++) acc[j] = 0ULL;
    float4 pa[8];
    float pb[8];
    const float* Arow = A + (size_t)la_m * lda + la_k;
    const float* Wcol = W + (size_t)lb_k * ldw + c0 + lb_n;
#pragma unroll
    for (int j = 0; j < 8; j++) pa[j] = *(const float4*)(Arow + 4 * j);
#pragma unroll
    for (int j = 0; j < 8; j++) pb[j] = Wcol[(size_t)(8 * j) * ldw];
    const int nc = K / KC;
    for (int ch = 0;;) {
#pragma unroll
        for (int j = 0; j < 8; j++) {
            float4 v = pa[j];
            int kk = la_k + 4 * j;
            As[(kk + 0) * 128 + la_m] = v.x;
            As[(kk + 1) * 128 + la_m] = v.y;
            As[(kk + 2) * 128 + la_m] = v.z;
            As[(kk + 3) * 128 + la_m] = v.w;
        }
#pragma unroll
        for (int j = 0; j < 8; j++) Bs[(lb_k + 8 * j) * 32 + lb_n] = make_float2(pb[j], pb[j]);
        __syncthreads();
        if (ch + 1 < nc) {
            const float* Ar2 = Arow + (ch + 1) * KC;
            const float* Wc2 = Wcol + (size_t)((ch + 1) * KC) * ldw;
#pragma unroll
            for (int j = 0; j < 8; j++) pa[j] = *(const float4*)(Ar2 + 4 * j);
#pragma unroll
            for (int j = 0; j < 8; j++) pb[j] = Wc2[(size_t)(8 * j) * ldw];
        }
        const ulonglong2* As2 = (const ulonglong2*)As;
        const ulonglong2* Bs2 = (const ulonglong2*)Bs;
#pragma unroll 8
        for (int k = 0; k < KC; k++) {
            ulonglong2 bv = Bs2[k * 16 + bi];
            ulonglong2 a01 = As2[k * 32 + ai];
            ulonglong2 a23 = As2[k * 32 + ai + 1];
            acc[0] = fma2(a01.x, bv.x, acc[0]);
            acc[1] = fma2(a01.x, bv.y, acc[1]);
            acc[2] = fma2(a01.y, bv.x, acc[2]);
            acc[3] = fma2(a01.y, bv.y, acc[3]);
            acc[4] = fma2(a23.x, bv.x, acc[4]);
            acc[5] = fma2(a23.x, bv.y, acc[5]);
            acc[6] = fma2(a23.y, bv.x, acc[6]);
            acc[7] = fma2(a23.y, bv.y, acc[7]);
        }
        __syncthreads();
        if (++ch == nc) break;
    }
}

// write helper: thread tile rows m8..m8+7 (pairs), cols c0+n2, c0+n2+1
__device__ __forceinline__ void store_tile_raw(float* out, int ldo, int c0,
                                               const unsigned long long acc[8]) {
    int tid = threadIdx.x;
    int m8 = (tid >> 4) * 8, n2 = (tid & 15) * 2;
#pragma unroll
    for (int mp = 0; mp < 4; mp++)
#pragma unroll
        for (int nn = 0; nn < 2; nn++) {
            float2 v = unpack2(acc[mp * 2 + nn]);
            int r = m8 + 2 * mp, c = c0 + n2 + nn;
            out[(size_t)r * ldo + c] = v.x;
            out[(size_t)(r + 1) * ldo + c] = v.y;
        }
}

// ---------------- init: mean_enc, WfcT, lstmb, flags ----------------
__global__ void k_init(const float* __restrict__ enc, const float* __restrict__ Wfc,
                       const float* __restrict__ bih, const float* __restrict__ bhh) {
    int bx = blockIdx.x, tid = threadIdx.x;  // 512 threads
    if (bx < NB) {
        const float* eb = enc + (size_t)bx * NP * NENC + tid;
        float s0 = 0.f, s1 = 0.f, s2 = 0.f, s3 = 0.f, s4 = 0.f;
#pragma unroll 5
        for (int p = 0; p < NP; p += 5) {
            s0 += eb[(size_t)(p + 0) * NENC];
            s1 += eb[(size_t)(p + 1) * NENC];
            s2 += eb[(size_t)(p + 2) * NENC];
            s3 += eb[(size_t)(p + 3) * NENC];
            s4 += eb[(size_t)(p + 4) * NENC];
        }
        g_mean[bx * NENC + tid] = (((s0 + s1) + (s2 + s3)) + s4) / 625.0f;
        if (tid == 0) {
            g_rowval[bx] = -INFINITY;
            g_rowflat[bx] = 0;
            g_tok[bx] = START_TOK;
        }
        if (bx == 0 && tid == 0) g_done[0] = 0;
    } else if (bx < NB + NV) {
        int col = bx - NB;
        g_WfcT[col * NH + tid] = Wfc[tid * NV + col];
    } else {
        int j = (bx - NB - NV) * 512 + tid;
        g_lstmb[j] = bih[j] + bhh[j];
    }
}

// ---------------- embW = emb @ Wih[0:256,:]  (one-time) ----------------
__global__ void k_embW(const float* __restrict__ emb, const float* __restrict__ Wih) {
    int t = blockIdx.x, seg = blockIdx.y, tid = threadIdx.x;  // 512 threads
    __shared__ float es[NE];
    if (tid < NE) es[tid] = emb[t * NE + tid];
    __syncthreads();
    int col = seg * 512 + tid;
    float acc = 0.f;
#pragma unroll 8
    for (int k = 0; k < NE; k++) acc = fmaf(es[k], Wih[(size_t)k * NG + col], acc);
    g_embW[t * NG + col] = acc;
}

// ---------------- h0/c0 (one-time) ----------------
__global__ __launch_bounds__(256) void k_h0c0(const float* __restrict__ Wh0,
                                              const float* __restrict__ bh0,
                                              const float* __restrict__ Wc0,
                                              const float* __restrict__ bc0) {
    __shared__ __align__(16) float As[KC * 128];
    __shared__ __align__(16) float2 Bs[KC * 32];
    int bx = blockIdx.x, tid = threadIdx.x;
    unsigned long long acc[8];
    const float* W = (bx < 16) ? Wh0 : Wc0;
    const float* bias = (bx < 16) ? bh0 : bc0;
    float* out = (bx < 16) ? g_h : g_c;
    int c0 = (bx & 15) * 32;
    gemm128x32(g_mean, NENC, W, NH, c0, NENC, acc, As, Bs);
    int m8 = (tid >> 4) * 8, n2 = (tid & 15) * 2;
#pragma unroll
    for (int mp = 0; mp < 4; mp++)
#pragma unroll
        for (int nn = 0; nn < 2; nn++) {
            float2 v = unpack2(acc[mp * 2 + nn]);
            int r = m8 + 2 * mp, c = c0 + n2 + nn;
            out[r * NH + c] = v.x + bias[c];
            out[(r + 1) * NH + c] = v.y + bias[c];
        }
}

// ---------------- att1 = enc @ We + be (one-time) ----------------
__global__ __launch_bounds__(256) void k_att1(const float* __restrict__ enc,
                                              const float* __restrict__ We,
                                              const float* __restrict__ be) {
    __shared__ __align__(16) float As[KC * 128];
    __shared__ __align__(16) float2 Bs[KC * 32];
    int bx = blockIdx.x, tid = threadIdx.x;
    int mt = bx >> 3, c0 = (bx & 7) * 32;
    unsigned long long acc[8];
    gemm128x32(enc + (size_t)mt * 128 * NENC, NENC, We, NA, c0, NENC, acc, As, Bs);
    int m8 = (tid >> 4) * 8, n2 = (tid & 15) * 2;
    float* out = g_att1 + (size_t)mt * 128 * NA;
#pragma unroll
    for (int mp = 0; mp < 4; mp++)
#pragma unroll
        for (int nn = 0; nn < 2; nn++) {
            float2 v = unpack2(acc[mp * 2 + nn]);
            int r = m8 + 2 * mp, c = c0 + n2 + nn;
            out[(size_t)r * NA + c] = v.x + be[c];
            out[(size_t)(r + 1) * NA + c] = v.y + be[c];
        }
}

// ---------------- K1: att2/gate partial GEMMs (K-split x4) + done-flag update ----------------
__global__ __launch_bounds__(256, 2) void k_proj1(const float* __restrict__ Wd,
                                                  const float* __restrict__ Wb) {
    __shared__ __align__(16) float As[KC * 128];
    __shared__ __align__(16) float2 Bs[KC * 32];
    int bx = blockIdx.x, tid = threadIdx.x;
    if (bx == 0) {  // done flag from previous step's row argmaxes
        float* dv = As;
        int* dfi = (int*)(As + 192);
        if (tid < 128) {
            dv[tid] = g_rowval[tid];
            dfi[tid] = g_rowflat[tid];
        }
        __syncthreads();
        for (int s = 64; s > 0; s >>= 1) {
            if (tid < s) {
                float ov = dv[tid + s];
                int of = dfi[tid + s];
                if (ov > dv[tid] || (ov == dv[tid] && of < dfi[tid])) {
                    dv[tid] = ov;
                    dfi[tid] = of;
                }
            }
            __syncthreads();
        }
        if (tid == 0 && dfi[0] == END_TOK) g_done[0] = 1;
        __syncthreads();
    }
    int ks = bx & 3, tile = bx >> 2;  // 24 tiles x 4 K-splits
    unsigned long long acc[8];
    const float* A = g_h + ks * 128;
    if (tile < 8) {
        int c0 = tile * 32;
        gemm128x32(A, NH, Wd + (size_t)(ks * 128) * NA, NA, c0, 128, acc, As, Bs);
        store_tile_raw(g_a2p[ks], NA, c0, acc);
    } else {
        int c0 = (tile - 8) * 32;
        gemm128x32(A, NH, Wb + (size_t)(ks * 128) * NENC, NENC, c0, 128, acc, As, Bs);
        store_tile_raw(g_gtp[ks], NENC, c0, acc);
    }
}

// ---------------- K2: fused [attention (blocks 0-127)] + [h@Whh GEMM (blocks 128-255)] ----------------
__global__ __launch_bounds__(256, 2) void k_mid(const float* __restrict__ enc,
                                                const float* __restrict__ wf,
                                                const float* __restrict__ bd,
                                                const float* __restrict__ bb,
                                                const float* __restrict__ Whh) {
    __shared__ __align__(16) union {
        struct {
            float As[KC * 128];
            float2 Bs[KC * 32];
        } g;
        struct {
            float att2s[NA];
            float wfs[NA];
            float es[NP];
            float red[256];
            float4 part[128];
        } a;
    } sm;
    int bx = blockIdx.x, tid = threadIdx.x;
    if (bx >= NB) {
        // ---- Whh GEMM: 64 col-tiles x 2 K-splits ----
        int idx = bx - NB;
        int ks = idx & 1, tile = idx >> 1;
        unsigned long long acc[8];
        gemm128x32(g_h + ks * 256, NH, Whh + (size_t)(ks * 256) * NG, NG, tile * 32, 256, acc,
                   sm.g.As, sm.g.Bs);
        store_tile_raw(g_gw[ks], NG, tile * 32, acc);
        return;
    }
    // ---- attention for batch row b ----
    int b = bx, wid = tid >> 5, lane = tid & 31;
    sm.a.att2s[tid] = g_a2p[0][b * NA + tid] + g_a2p[1][b * NA + tid] + g_a2p[2][b * NA + tid] +
                      g_a2p[3][b * NA + tid] + bd[tid];
    sm.a.wfs[tid] = wf[tid];
    __syncthreads();
    const float4* base = (const float4*)(g_att1 + (size_t)b * NP * NA);
    float4 a0 = ((const float4*)sm.a.att2s)[lane], a1 = ((const float4*)sm.a.att2s)[32 + lane];
    float4 w0 = ((const float4*)sm.a.wfs)[lane], w1 = ((const float4*)sm.a.wfs)[32 + lane];
    for (int p0 = wid * 4; p0 < NP; p0 += 32) {
        float4 v[4][2];
#pragma unroll
        for (int u = 0; u < 4; u++) {
            int p = p0 + u;
            if (p < NP) {
                v[u][0] = base[(size_t)p * 64 + lane];
                v[u][1] = base[(size_t)p * 64 + 32 + lane];
            }
        }
#pragma unroll
        for (int u = 0; u < 4; u++) {
            int p = p0 + u;
            if (p < NP) {
                float s = fmaxf(v[u][0].x + a0.x, 0.f) * w0.x + fmaxf(v[u][0].y + a0.y, 0.f) * w0.y +
                          fmaxf(v[u][0].z + a0.z, 0.f) * w0.z + fmaxf(v[u][0].w + a0.w, 0.f) * w0.w +
                          fmaxf(v[u][1].x + a1.x, 0.f) * w1.x + fmaxf(v[u][1].y + a1.y, 0.f) * w1.y +
                          fmaxf(v[u][1].z + a1.z, 0.f) * w1.z + fmaxf(v[u][1].w + a1.w, 0.f) * w1.w;
#pragma unroll
                for (int o = 16; o > 0; o >>= 1) s += __shfl_down_sync(0xffffffffu, s, o);
                if (lane == 0) sm.a.es[p] = s;
            }
        }
    }
    __syncthreads();
    // softmax
    float m = -INFINITY;
    for (int i = tid; i < NP; i += 256) m = fmaxf(m, sm.a.es[i]);
    sm.a.red[tid] = m;
    __syncthreads();
    for (int s2 = 128; s2 > 0; s2 >>= 1) {
        if (tid < s2) sm.a.red[tid] = fmaxf(sm.a.red[tid], sm.a.red[tid + s2]);
        __syncthreads();
    }
    float M = sm.a.red[0];
    __syncthreads();
    float sum = 0.f;
    for (int i = tid; i < NP; i += 256) {
        float v = expf(sm.a.es[i] - M);
        sm.a.es[i] = v;
        sum += v;
    }
    sm.a.red[tid] = sum;
    __syncthreads();
    for (int s2 = 128; s2 > 0; s2 >>= 1) {
        if (tid < s2) sm.a.red[tid] += sm.a.red[tid + s2];
        __syncthreads();
    }
    float inv = 1.f / sm.a.red[0];
    __syncthreads();
    for (int i = tid; i < NP; i += 256) sm.a.es[i] *= inv;
    __syncthreads();
    // awe = alpha @ enc (2 p-groups), then gate and write g_x
    int q = tid & 127, pg = tid >> 7;
    const float4* eb = (const float4*)(enc + (size_t)b * NP * NENC);
    float4 acc = make_float4(0.f, 0.f, 0.f, 0.f);
#pragma unroll 4
    for (int p = pg; p < NP; p += 2) {
        float al = sm.a.es[p];
        float4 l = eb[(size_t)p * 128 + q];
        acc.x += al * l.x;
        acc.y += al * l.y;
        acc.z += al * l.z;
        acc.w += al * l.w;
    }
    if (pg == 1) sm.a.part[q] = acc;
    __syncthreads();
    if (pg == 0) {
        float4 p1 = sm.a.part[q];
        float4 gp0 = *(const float4*)(g_gtp[0] + b * NENC + 4 * q);
        float4 gp1 = *(const float4*)(g_gtp[1] + b * NENC + 4 * q);
        float4 gp2 = *(const float4*)(g_gtp[2] + b * NENC + 4 * q);
        float4 gp3 = *(const float4*)(g_gtp[3] + b * NENC + 4 * q);
        float4 bbv = *(const float4*)(bb + 4 * q);
        float gx = sigmoidf_(gp0.x + gp1.x + gp2.x + gp3.x + bbv.x);
        float gy = sigmoidf_(gp0.y + gp1.y + gp2.y + gp3.y + bbv.y);
        float gz = sigmoidf_(gp0.z + gp1.z + gp2.z + gp3.z + bbv.z);
        float gw = sigmoidf_(gp0.w + gp1.w + gp2.w + gp3.w + bbv.w);
        float4 o = make_float4((acc.x + p1.x) * gx, (acc.y + p1.y) * gy, (acc.z + p1.z) * gz,
                               (acc.w + p1.w) * gw);
        *(float4*)(g_x + b * NH + 4 * q) = o;
    }
}

// ---------------- K3: awe @ Wih[256:768]  (64 col-tiles x 2 K-splits) ----------------
__global__ __launch_bounds__(256, 2) void k_wih(const float* __restrict__ Wih) {
    __shared__ __align__(16) float As[KC * 128];
    __shared__ __align__(16) float2 Bs[KC * 32];
    int bx = blockIdx.x;
    int ks = bx & 1, tile = bx >> 1;
    unsigned long long acc[8];
    gemm128x32(g_x + ks * 256, NH, Wih + (size_t)(NE + ks * 256) * NG, NG, tile * 32, 256, acc,
               As, Bs);
    store_tile_raw(g_wp[ks], NG, tile * 32, acc);
}

// ---------------- K4: gate-sum + LSTM + preds + argmax + token feedback ----------------
__global__ __launch_bounds__(512) void k_step(const float* __restrict__ bfc,
                                              float* __restrict__ out, int t) {
    int b = blockIdx.x, tid = threadIdx.x, wid = tid >> 5, lane = tid & 31;
    __shared__ __align__(16) float hs[NH];
    __shared__ float pv[128];
    __shared__ int pi_[128];
    __shared__ int widx;
    int tok = g_tok[b];
    {
        int j = tid;
        const float* w0 = g_gw[0] + b * NG;
        const float* w1 = g_gw[1] + b * NG;
        const float* p0 = g_wp[0] + b * NG;
        const float* p1 = g_wp[1] + b * NG;
        const float* ew = g_embW + tok * NG;
        float iv = w0[j] + w1[j] + p0[j] + p1[j] + ew[j] + g_lstmb[j];
        float fv = w0[j + 512] + w1[j + 512] + p0[j + 512] + p1[j + 512] + ew[j + 512] +
                   g_lstmb[j + 512];
        float gv = w0[j + 1024] + w1[j + 1024] + p0[j + 1024] + p1[j + 1024] + ew[j + 1024] +
                   g_lstmb[j + 1024];
        float ov = w0[j + 1536] + w1[j + 1536] + p0[j + 1536] + p1[j + 1536] + ew[j + 1536] +
                   g_lstmb[j + 1536];
        float c = g_c[b * NH + j];
        float cn = sigmoidf_(fv) * c + sigmoidf_(iv) * tanhf(gv);
        float hn = sigmoidf_(ov) * tanhf(cn);
        g_c[b * NH + j] = cn;
        g_h[b * NH + j] = hn;
        hs[j] = hn;
    }
    if (tid < 128) {
        pv[tid] = -INFINITY;
        pi_[tid] = tid;
    }
    __syncthreads();
    int done = g_done[0];
    const float4* hs4 = (const float4*)hs;
    for (int col = wid; col < NV; col += 16) {
        const float4* wr = (const float4*)(g_WfcT + col * NH);
        float s = 0.f;
#pragma unroll
        for (int i = 0; i < 4; i++) {
            float4 h4 = hs4[lane + 32 * i];
            float4 w4 = wr[lane + 32 * i];
            s += h4.x * w4.x + h4.y * w4.y + h4.z * w4.z + h4.w * w4.w;
        }
#pragma unroll
        for (int o = 16; o > 0; o >>= 1) s += __shfl_down_sync(0xffffffffu, s, o);
        if (lane == 0) {
            s += bfc[col];
            out[(size_t)b * NT * NV + (size_t)t * NV + col] = done ? 0.f : s;
            pv[col] = s;
            pi_[col] = col;
        }
    }
    __syncthreads();
    for (int s2 = 64; s2 > 0; s2 >>= 1) {
        if (tid < s2) {
            float ov = pv[tid + s2];
            int oi = pi_[tid + s2];
            if (ov > pv[tid] || (ov == pv[tid] && oi < pi_[tid])) {
                pv[tid] = ov;
                pi_[tid] = oi;
            }
        }
        __syncthreads();
    }
    if (tid == 0) {
        g_rowval[b] = pv[0];
        g_rowflat[b] = b * NV + pi_[0];
        g_tok[b] = pi_[0];
    }
}

extern "C" void kernel_launch(void* const* d_in, const int* in_sizes, int n_in,
                              void* d_out, int out_size) {
    (void)in_sizes; (void)n_in; (void)out_size;
    const float* enc = (const float*)d_in[0];
    const float* emb = (const float*)d_in[1];
    const float* We  = (const float*)d_in[2];
    const float* be  = (const float*)d_in[3];
    const float* Wd  = (const float*)d_in[4];
    const float* bd  = (const float*)d_in[5];
    const float* wf  = (const float*)d_in[6];
    const float* Wh0 = (const float*)d_in[8];
    const float* bh0 = (const float*)d_in[9];
    const float* Wc0 = (const float*)d_in[10];
    const float* bc0 = (const float*)d_in[11];
    const float* Wb  = (const float*)d_in[12];
    const float* bb  = (const float*)d_in[13];
    const float* Wih = (const float*)d_in[14];
    const float* Whh = (const float*)d_in[15];
    const float* bih = (const float*)d_in[16];
    const float* bhh = (const float*)d_in[17];
    const float* Wfc = (const float*)d_in[18];
    const float* bfc = (const float*)d_in[19];
    float* out = (float*)d_out;

    k_init<<<NB + NV + 4, 512>>>(enc, Wfc, bih, bhh);
    k_embW<<<dim3(NV, 4), 512>>>(emb, Wih);
    k_att1<<<5000, 256>>>(enc, We, be);
    k_h0c0<<<32, 256>>>(Wh0, bh0, Wc0, bc0);
    for (int t = 0; t < NT; t++) {
        k_proj1<<<96, 256>>>(Wd, Wb);
        k_mid<<<256, 256>>>(enc, wf, bd, bb, Whh);
        k_wih<<<128, 256>>>(Wih);
        k_step<<<NB, 512>>>(bfc, out, t);
    }
}

// round 8
// speedup vs baseline: 1.0688x; 1.0688x over previous
#include <cuda_runtime.h>
#include <math.h>

#define NB 128
#define NP 625
#define NENC 512
#define NA 256
#define NE 256
#define NH 512
#define NV 70
#define NT 70
#define NG 2048
#define KC 64
#define START_TOK 68
#define END_TOK 69

// ---------------- scratch ----------------
__device__ float g_att1[NB * NP * NA];   // 81.92MB
__device__ float g_h[NB * NH];
__device__ float g_c[NB * NH];
__device__ float g_mean[NB * NENC];
__device__ float g_x[NB * NH];           // gated awe
__device__ float g_e[NB * NP];           // attention energies
__device__ float g_a2p[4][NB * NA];      // att2 K-partials
__device__ float g_gtp[4][NB * NENC];    // gate  K-partials
__device__ float g_gw[2][NB * NG];       // h@Whh K-partials
__device__ float g_wp[2][NB * NG];       // awe@Wih2 K-partials
__device__ float g_embW[NV * NG];        // emb @ Wih[0:256] per vocab token
__device__ float g_lstmb[NG];            // bih + bhh
__device__ float g_WfcT[NV * NH];
__device__ float g_rowval[NB];
__device__ int   g_rowflat[NB];
__device__ int   g_tok[NB];
__device__ int   g_done[1];

// ---------------- f32x2 helpers ----------------
__device__ __forceinline__ unsigned long long fma2(unsigned long long a, unsigned long long b,
                                                   unsigned long long c) {
    unsigned long long d;
    asm("fma.rn.f32x2 %0, %1, %2, %3;" : "=l"(d) : "l"(a), "l"(b), "l"(c));
    return d;
}
__device__ __forceinline__ float2 unpack2(unsigned long long v) {
    float2 r;
    asm("mov.b64 {%0, %1}, %2;" : "=f"(r.x), "=f"(r.y) : "l"(v));
    return r;
}
__device__ __forceinline__ float sigmoidf_(float x) { return 1.f / (1.f + expf(-x)); }

// ---------------- core GEMM tile: C[128, c0:c0+32] = A[128,K] @ W[K, ldw] ----------------
__device__ __forceinline__ void gemm128x32(const float* __restrict__ A, int lda,
                                           const float* __restrict__ W, int ldw, int c0, int K,
                                           unsigned long long acc[8], float* As, float2* Bs) {
    const int tid = threadIdx.x;
    const int ai = (tid >> 4) * 2;
    const int bi = tid & 15;
    const int la_m = tid & 127, la_k = (tid >> 7) * 32;
    const int lb_n = tid & 31, lb_k = tid >> 5;
#pragma unroll
    for (int j = 0; j < 8; j++) acc[j] = 0ULL;
    float4 pa[8];
    float pb[8];
    const float* Arow = A + (size_t)la_m * lda + la_k;
    const float* Wcol = W + (size_t)lb_k * ldw + c0 + lb_n;
#pragma unroll
    for (int j = 0; j < 8; j++) pa[j] = *(const float4*)(Arow + 4 * j);
#pragma unroll
    for (int j = 0; j < 8; j++) pb[j] = Wcol[(size_t)(8 * j) * ldw];
    const int nc = K / KC;
    for (int ch = 0;;) {
#pragma unroll
        for (int j = 0; j < 8; j++) {
            float4 v = pa[j];
            int kk = la_k + 4 * j;
            As[(kk + 0) * 128 + la_m] = v.x;
            As[(kk + 1) * 128 + la_m] = v.y;
            As[(kk + 2) * 128 + la_m] = v.z;
            As[(kk + 3) * 128 + la_m] = v.w;
        }
#pragma unroll
        for (int j = 0; j < 8; j++) Bs[(lb_k + 8 * j) * 32 + lb_n] = make_float2(pb[j], pb[j]);
        __syncthreads();
        if (ch + 1 < nc) {
            const float* Ar2 = Arow + (ch + 1) * KC;
            const float* Wc2 = Wcol + (size_t)((ch + 1) * KC) * ldw;
#pragma unroll
            for (int j = 0; j < 8; j++) pa[j] = *(const float4*)(Ar2 + 4 * j);
#pragma unroll
            for (int j = 0; j < 8; j++) pb[j] = Wc2[(size_t)(8 * j) * ldw];
        }
        const ulonglong2* As2 = (const ulonglong2*)As;
        const ulonglong2* Bs2 = (const ulonglong2*)Bs;
#pragma unroll 8
        for (int k = 0; k < KC; k++) {
            ulonglong2 bv = Bs2[k * 16 + bi];
            ulonglong2 a01 = As2[k * 32 + ai];
            ulonglong2 a23 = As2[k * 32 + ai + 1];
            acc[0] = fma2(a01.x, bv.x, acc[0]);
            acc[1] = fma2(a01.x, bv.y, acc[1]);
            acc[2] = fma2(a01.y, bv.x, acc[2]);
            acc[3] = fma2(a01.y, bv.y, acc[3]);
            acc[4] = fma2(a23.x, bv.x, acc[4]);
            acc[5] = fma2(a23.x, bv.y, acc[5]);
            acc[6] = fma2(a23.y, bv.x, acc[6]);
            acc[7] = fma2(a23.y, bv.y, acc[7]);
        }
        __syncthreads();
        if (++ch == nc) break;
    }
}

__device__ __forceinline__ void store_tile_raw(float* out, int ldo, int c0,
                                               const unsigned long long acc[8]) {
    int tid = threadIdx.x;
    int m8 = (tid >> 4) * 8, n2 = (tid & 15) * 2;
#pragma unroll
    for (int mp = 0; mp < 4; mp++)
#pragma unroll
        for (int nn = 0; nn < 2; nn++) {
            float2 v = unpack2(acc[mp * 2 + nn]);
            int r = m8 + 2 * mp, c = c0 + n2 + nn;
            out[(size_t)r * ldo + c] = v.x;
            out[(size_t)(r + 1) * ldo + c] = v.y;
        }
}

// ---------------- init: mean_enc, WfcT, lstmb, embW, flags (one launch) ----------------
__global__ void k_init(const float* __restrict__ enc, const float* __restrict__ Wfc,
                       const float* __restrict__ bih, const float* __restrict__ bhh,
                       const float* __restrict__ emb, const float* __restrict__ Wih) {
    __shared__ float es[NE];
    int bx = blockIdx.x, tid = threadIdx.x;  // 512 threads
    if (bx < NB) {
        const float* eb = enc + (size_t)bx * NP * NENC + tid;
        float s0 = 0.f, s1 = 0.f, s2 = 0.f, s3 = 0.f, s4 = 0.f;
#pragma unroll 5
        for (int p = 0; p < NP; p += 5) {
            s0 += eb[(size_t)(p + 0) * NENC];
            s1 += eb[(size_t)(p + 1) * NENC];
            s2 += eb[(size_t)(p + 2) * NENC];
            s3 += eb[(size_t)(p + 3) * NENC];
            s4 += eb[(size_t)(p + 4) * NENC];
        }
        g_mean[bx * NENC + tid] = (((s0 + s1) + (s2 + s3)) + s4) / 625.0f;
        if (tid == 0) {
            g_rowval[bx] = -INFINITY;
            g_rowflat[bx] = 0;
            g_tok[bx] = START_TOK;
        }
        if (bx == 0 && tid == 0) g_done[0] = 0;
    } else if (bx < NB + NV) {
        int col = bx - NB;
        g_WfcT[col * NH + tid] = Wfc[tid * NV + col];
    } else if (bx < NB + NV + 4) {
        int j = (bx - NB - NV) * 512 + tid;
        g_lstmb[j] = bih[j] + bhh[j];
    } else {
        int idx = bx - (NB + NV + 4);
        int t = idx >> 2, seg = idx & 3;
        if (tid < NE) es[tid] = emb[t * NE + tid];
        __syncthreads();
        int col = seg * 512 + tid;
        float acc = 0.f;
#pragma unroll 8
        for (int k = 0; k < NE; k++) acc = fmaf(es[k], Wih[(size_t)k * NG + col], acc);
        g_embW[t * NG + col] = acc;
    }
}

// ---------------- att1 = enc @ We + be  +  h0/c0 (merged, one launch) ----------------
__global__ __launch_bounds__(256) void k_att1(const float* __restrict__ enc,
                                              const float* __restrict__ We,
                                              const float* __restrict__ be,
                                              const float* __restrict__ Wh0,
                                              const float* __restrict__ bh0,
                                              const float* __restrict__ Wc0,
                                              const float* __restrict__ bc0) {
    __shared__ __align__(16) float As[KC * 128];
    __shared__ __align__(16) float2 Bs[KC * 32];
    int bx = blockIdx.x, tid = threadIdx.x;
    unsigned long long acc[8];
    int m8 = (tid >> 4) * 8, n2 = (tid & 15) * 2;
    if (bx < 5000) {
        int mt = bx >> 3, c0 = (bx & 7) * 32;
        gemm128x32(enc + (size_t)mt * 128 * NENC, NENC, We, NA, c0, NENC, acc, As, Bs);
        float* out = g_att1 + (size_t)mt * 128 * NA;
#pragma unroll
        for (int mp = 0; mp < 4; mp++)
#pragma unroll
            for (int nn = 0; nn < 2; nn++) {
                float2 v = unpack2(acc[mp * 2 + nn]);
                int r = m8 + 2 * mp, c = c0 + n2 + nn;
                out[(size_t)r * NA + c] = v.x + be[c];
                out[(size_t)(r + 1) * NA + c] = v.y + be[c];
            }
    } else {
        int b2 = bx - 5000;
        const float* W = (b2 < 16) ? Wh0 : Wc0;
        const float* bias = (b2 < 16) ? bh0 : bc0;
        float* out = (b2 < 16) ? g_h : g_c;
        int c0 = (b2 & 15) * 32;
        gemm128x32(g_mean, NENC, W, NH, c0, NENC, acc, As, Bs);
#pragma unroll
        for (int mp = 0; mp < 4; mp++)
#pragma unroll
            for (int nn = 0; nn < 2; nn++) {
                float2 v = unpack2(acc[mp * 2 + nn]);
                int r = m8 + 2 * mp, c = c0 + n2 + nn;
                out[r * NH + c] = v.x + bias[c];
                out[(r + 1) * NH + c] = v.y + bias[c];
            }
    }
}

// ---------------- K1: att2 partial GEMMs (8 tiles x 4 Ksplit) + done-flag ----------------
__global__ __launch_bounds__(256, 2) void k_proj1(const float* __restrict__ Wd) {
    __shared__ __align__(16) float As[KC * 128];
    __shared__ __align__(16) float2 Bs[KC * 32];
    int bx = blockIdx.x, tid = threadIdx.x;
    if (bx == 0) {
        float* dv = As;
        int* dfi = (int*)(As + 192);
        if (tid < 128) {
            dv[tid] = g_rowval[tid];
            dfi[tid] = g_rowflat[tid];
        }
        __syncthreads();
        for (int s = 64; s > 0; s >>= 1) {
            if (tid < s) {
                float ov = dv[tid + s];
                int of = dfi[tid + s];
                if (ov > dv[tid] || (ov == dv[tid] && of < dfi[tid])) {
                    dv[tid] = ov;
                    dfi[tid] = of;
                }
            }
            __syncthreads();
        }
        if (tid == 0 && dfi[0] == END_TOK) g_done[0] = 1;
        __syncthreads();
    }
    int ks = bx & 3, tile = bx >> 2;
    unsigned long long acc[8];
    gemm128x32(g_h + ks * 128, NH, Wd + (size_t)(ks * 128) * NA, NA, tile * 32, 128, acc, As, Bs);
    store_tile_raw(g_a2p[ks], NA, tile * 32, acc);
}

// ---------------- K2: e-pass (640 blocks) + Whh GEMM (128) + Wb gate partials (64) ----------------
__global__ __launch_bounds__(256, 2) void k_epass(const float* __restrict__ wf,
                                                  const float* __restrict__ bd,
                                                  const float* __restrict__ Whh,
                                                  const float* __restrict__ Wb) {
    __shared__ __align__(16) union {
        struct {
            float As[KC * 128];
            float2 Bs[KC * 32];
        } g;
        struct {
            float att2s[NA];
            float wfs[NA];
        } a;
    } sm;
    int bx = blockIdx.x, tid = threadIdx.x;
    if (bx < 128) {  // Whh: 64 col-tiles x 2 K-splits
        int ks = bx & 1, tile = bx >> 1;
        unsigned long long acc[8];
        gemm128x32(g_h + ks * 256, NH, Whh + (size_t)(ks * 256) * NG, NG, tile * 32, 256, acc,
                   sm.g.As, sm.g.Bs);
        store_tile_raw(g_gw[ks], NG, tile * 32, acc);
        return;
    }
    if (bx < 192) {  // Wb gate partials: 16 tiles x 4 K-splits
        int idx = bx - 128;
        int ks = idx & 3, tile = idx >> 2;
        unsigned long long acc[8];
        gemm128x32(g_h + ks * 128, NH, Wb + (size_t)(ks * 128) * NENC, NENC, tile * 32, 128, acc,
                   sm.g.As, sm.g.Bs);
        store_tile_raw(g_gtp[ks], NENC, tile * 32, acc);
        return;
    }
    // attention e-pass: block handles 125 p's of one batch row
    int idx = bx - 192;
    int b = idx / 5, chunk = idx - b * 5;
    int pstart = chunk * 125, pend = pstart + 125;
    sm.a.att2s[tid] = g_a2p[0][b * NA + tid] + g_a2p[1][b * NA + tid] + g_a2p[2][b * NA + tid] +
                      g_a2p[3][b * NA + tid] + bd[tid];
    sm.a.wfs[tid] = wf[tid];
    __syncthreads();
    int wid = tid >> 5, lane = tid & 31;
    const float4* base = (const float4*)(g_att1 + (size_t)b * NP * NA);
    float4 a0 = ((const float4*)sm.a.att2s)[lane], a1 = ((const float4*)sm.a.att2s)[32 + lane];
    float4 w0 = ((const float4*)sm.a.wfs)[lane], w1 = ((const float4*)sm.a.wfs)[32 + lane];
    int p0 = pstart + wid * 16;
#pragma unroll
    for (int i = 0; i < 16; i += 2) {
        int p = p0 + i;
        float4 u0, u1, v0, v1;
        bool ok0 = p < pend, ok1 = (p + 1) < pend;
        if (ok0) {
            u0 = base[(size_t)p * 64 + lane];
            u1 = base[(size_t)p * 64 + 32 + lane];
        }
        if (ok1) {
            v0 = base[(size_t)(p + 1) * 64 + lane];
            v1 = base[(size_t)(p + 1) * 64 + 32 + lane];
        }
        if (ok0) {
            float s = fmaxf(u0.x + a0.x, 0.f) * w0.x + fmaxf(u0.y + a0.y, 0.f) * w0.y +
                      fmaxf(u0.z + a0.z, 0.f) * w0.z + fmaxf(u0.w + a0.w, 0.f) * w0.w +
                      fmaxf(u1.x + a1.x, 0.f) * w1.x + fmaxf(u1.y + a1.y, 0.f) * w1.y +
                      fmaxf(u1.z + a1.z, 0.f) * w1.z + fmaxf(u1.w + a1.w, 0.f) * w1.w;
#pragma unroll
            for (int o = 16; o > 0; o >>= 1) s += __shfl_down_sync(0xffffffffu, s, o);
            if (lane == 0) g_e[b * NP + p] = s;
        }
        if (ok1) {
            float s = fmaxf(v0.x + a0.x, 0.f) * w0.x + fmaxf(v0.y + a0.y, 0.f) * w0.y +
                      fmaxf(v0.z + a0.z, 0.f) * w0.z + fmaxf(v0.w + a0.w, 0.f) * w0.w +
                      fmaxf(v1.x + a1.x, 0.f) * w1.x + fmaxf(v1.y + a1.y, 0.f) * w1.y +
                      fmaxf(v1.z + a1.z, 0.f) * w1.z + fmaxf(v1.w + a1.w, 0.f) * w1.w;
#pragma unroll
            for (int o = 16; o > 0; o >>= 1) s += __shfl_down_sync(0xffffffffu, s, o);
            if (lane == 0) g_e[b * NP + p + 1] = s;
        }
    }
}

// ---------------- K3: softmax + awe + gate  (128 blocks x 512 threads) ----------------
__global__ __launch_bounds__(512) void k_smaw(const float* __restrict__ enc,
                                              const float* __restrict__ bb) {
    int b = blockIdx.x, tid = threadIdx.x;
    __shared__ float es[NP];
    __shared__ float red[512];
    __shared__ __align__(16) float4 part[3][128];
    for (int i = tid; i < NP; i += 512) es[i] = g_e[b * NP + i];
    __syncthreads();
    float m = -INFINITY;
    for (int i = tid; i < NP; i += 512) m = fmaxf(m, es[i]);
    red[tid] = m;
    __syncthreads();
    for (int s2 = 256; s2 > 0; s2 >>= 1) {
        if (tid < s2) red[tid] = fmaxf(red[tid], red[tid + s2]);
        __syncthreads();
    }
    float M = red[0];
    __syncthreads();
    float sum = 0.f;
    for (int i = tid; i < NP; i += 512) {
        float v = expf(es[i] - M);
        es[i] = v;
        sum += v;
    }
    red[tid] = sum;
    __syncthreads();
    for (int s2 = 256; s2 > 0; s2 >>= 1) {
        if (tid < s2) red[tid] += red[tid + s2];
        __syncthreads();
    }
    float inv = 1.f / red[0];
    __syncthreads();
    for (int i = tid; i < NP; i += 512) es[i] *= inv;
    __syncthreads();
    // awe = alpha @ enc, 4 p-groups x 128 q
    int q = tid & 127, pg = tid >> 7;
    const float4* eb = (const float4*)(enc + (size_t)b * NP * NENC);
    float4 acc = make_float4(0.f, 0.f, 0.f, 0.f);
#pragma unroll 8
    for (int p = pg; p < NP; p += 4) {
        float al = es[p];
        float4 l = eb[(size_t)p * 128 + q];
        acc.x += al * l.x;
        acc.y += al * l.y;
        acc.z += al * l.z;
        acc.w += al * l.w;
    }
    if (pg > 0) part[pg - 1][q] = acc;
    __syncthreads();
    if (pg == 0) {
        float4 p1 = part[0][q], p2 = part[1][q], p3 = part[2][q];
        acc.x += p1.x + p2.x + p3.x;
        acc.y += p1.y + p2.y + p3.y;
        acc.z += p1.z + p2.z + p3.z;
        acc.w += p1.w + p2.w + p3.w;
        float4 gp0 = *(const float4*)(g_gtp[0] + b * NENC + 4 * q);
        float4 gp1 = *(const float4*)(g_gtp[1] + b * NENC + 4 * q);
        float4 gp2 = *(const float4*)(g_gtp[2] + b * NENC + 4 * q);
        float4 gp3 = *(const float4*)(g_gtp[3] + b * NENC + 4 * q);
        float4 bbv = *(const float4*)(bb + 4 * q);
        float gx = sigmoidf_(gp0.x + gp1.x + gp2.x + gp3.x + bbv.x);
        float gy = sigmoidf_(gp0.y + gp1.y + gp2.y + gp3.y + bbv.y);
        float gz = sigmoidf_(gp0.z + gp1.z + gp2.z + gp3.z + bbv.z);
        float gw = sigmoidf_(gp0.w + gp1.w + gp2.w + gp3.w + bbv.w);
        float4 o = make_float4(acc.x * gx, acc.y * gy, acc.z * gz, acc.w * gw);
        *(float4*)(g_x + b * NH + 4 * q) = o;
    }
}

// ---------------- K4: awe @ Wih[256:768]  (64 col-tiles x 2 K-splits) ----------------
__global__ __launch_bounds__(256, 2) void k_wih(const float* __restrict__ Wih) {
    __shared__ __align__(16) float As[KC * 128];
    __shared__ __align__(16) float2 Bs[KC * 32];
    int bx = blockIdx.x;
    int ks = bx & 1, tile = bx >> 1;
    unsigned long long acc[8];
    gemm128x32(g_x + ks * 256, NH, Wih + (size_t)(NE + ks * 256) * NG, NG, tile * 32, 256, acc,
               As, Bs);
    store_tile_raw(g_wp[ks], NG, tile * 32, acc);
}

// ---------------- K5: gate-sum + LSTM + preds + argmax + token feedback ----------------
__global__ __launch_bounds__(512) void k_step(const float* __restrict__ bfc,
                                              float* __restrict__ out, int t) {
    int b = blockIdx.x, tid = threadIdx.x, wid = tid >> 5, lane = tid & 31;
    __shared__ __align__(16) float hs[NH];
    __shared__ float pv[128];
    __shared__ int pi_[128];
    int tok = g_tok[b];
    {
        int j = tid;
        const float* w0 = g_gw[0] + b * NG;
        const float* w1 = g_gw[1] + b * NG;
        const float* p0 = g_wp[0] + b * NG;
        const float* p1 = g_wp[1] + b * NG;
        const float* ew = g_embW + tok * NG;
        float iv = w0[j] + w1[j] + p0[j] + p1[j] + ew[j] + g_lstmb[j];
        float fv = w0[j + 512] + w1[j + 512] + p0[j + 512] + p1[j + 512] + ew[j + 512] +
                   g_lstmb[j + 512];
        float gv = w0[j + 1024] + w1[j + 1024] + p0[j + 1024] + p1[j + 1024] + ew[j + 1024] +
                   g_lstmb[j + 1024];
        float ov = w0[j + 1536] + w1[j + 1536] + p0[j + 1536] + p1[j + 1536] + ew[j + 1536] +
                   g_lstmb[j + 1536];
        float c = g_c[b * NH + j];
        float cn = sigmoidf_(fv) * c + sigmoidf_(iv) * tanhf(gv);
        float hn = sigmoidf_(ov) * tanhf(cn);
        g_c[b * NH + j] = cn;
        g_h[b * NH + j] = hn;
        hs[j] = hn;
    }
    if (tid < 128) {
        pv[tid] = -INFINITY;
        pi_[tid] = tid;
    }
    __syncthreads();
    int done = g_done[0];
    const float4* hs4 = (const float4*)hs;
    for (int col = wid; col < NV; col += 16) {
        const float4* wr = (const float4*)(g_WfcT + col * NH);
        float s = 0.f;
#pragma unroll
        for (int i = 0; i < 4; i++) {
            float4 h4 = hs4[lane + 32 * i];
            float4 w4 = wr[lane + 32 * i];
            s += h4.x * w4.x + h4.y * w4.y + h4.z * w4.z + h4.w * w4.w;
        }
#pragma unroll
        for (int o = 16; o > 0; o >>= 1) s += __shfl_down_sync(0xffffffffu, s, o);
        if (lane == 0) {
            s += bfc[col];
            out[(size_t)b * NT * NV + (size_t)t * NV + col] = done ? 0.f : s;
            pv[col] = s;
            pi_[col] = col;
        }
    }
    __syncthreads();
    for (int s2 = 64; s2 > 0; s2 >>= 1) {
        if (tid < s2) {
            float ov = pv[tid + s2];
            int oi = pi_[tid + s2];
            if (ov > pv[tid] || (ov == pv[tid] && oi < pi_[tid])) {
                pv[tid] = ov;
                pi_[tid] = oi;
            }
        }
        __syncthreads();
    }
    if (tid == 0) {
        g_rowval[b] = pv[0];
        g_rowflat[b] = b * NV + pi_[0];
        g_tok[b] = pi_[0];
    }
}

extern "C" void kernel_launch(void* const* d_in, const int* in_sizes, int n_in,
                              void* d_out, int out_size) {
    (void)in_sizes; (void)n_in; (void)out_size;
    const float* enc = (const float*)d_in[0];
    const float* emb = (const float*)d_in[1];
    const float* We  = (const float*)d_in[2];
    const float* be  = (const float*)d_in[3];
    const float* Wd  = (const float*)d_in[4];
    const float* bd  = (const float*)d_in[5];
    const float* wf  = (const float*)d_in[6];
    const float* Wh0 = (const float*)d_in[8];
    const float* bh0 = (const float*)d_in[9];
    const float* Wc0 = (const float*)d_in[10];
    const float* bc0 = (const float*)d_in[11];
    const float* Wb  = (const float*)d_in[12];
    const float* bb  = (const float*)d_in[13];
    const float* Wih = (const float*)d_in[14];
    const float* Whh = (const float*)d_in[15];
    const float* bih = (const float*)d_in[16];
    const float* bhh = (const float*)d_in[17];
    const float* Wfc = (const float*)d_in[18];
    const float* bfc = (const float*)d_in[19];
    float* out = (float*)d_out;

    k_init<<<NB + NV + 4 + NV * 4, 512>>>(enc, Wfc, bih, bhh, emb, Wih);
    k_att1<<<5032, 256>>>(enc, We, be, Wh0, bh0, Wc0, bc0);
    for (int t = 0; t < NT; t++) {
        k_proj1<<<32, 256>>>(Wd);
        k_epass<<<832, 256>>>(wf, bd, Whh, Wb);
        k_smaw<<<NB, 512>>>(enc, bb);
        k_wih<<<128, 256>>>(Wih);
        k_step<<<NB, 512>>>(bfc, out, t);
    }
}